// round 14
// baseline (speedup 1.0000x reference)
#include <cuda_runtime.h>
#include <cuda_fp16.h>
#include <cstdint>

#define NTH  128
#define NHID 6

// fp16 operands, 128x128, rows of 128 halves = 256B, XOR-swizzled:
//   byte(row, kh) = row*256 + (((kh>>3) ^ (row&7))<<4) + (kh&7)*2
#define B_ADJ   0
#define B_ACT   32768
#define B_WT    65536
#define B_X0    98304       // 128 rows x 32B (16 halves), unswizzled
#define B_WINT  102400      // 128 rows x 32B
// float-indexed misc
#define F_BIN   26624       // 128
#define F_BIA   26752       // 768 (pre-scaled by 8^-(l+1))
#define F_MSK   27520       // 128
#define F_WO    27648       // 128
#define F_RED   28032       // 8 (RED[7] = denom)
#define F_BOUT  28040
#define SMEM_BYTES 112192

__device__ __forceinline__ uint32_t smem_u32(const void* p) {
    uint32_t a;
    asm("{ .reg .u64 t; cvta.to.shared.u64 t, %1; cvt.u32.u64 %0, t; }" : "=r"(a) : "l"(p));
    return a;
}

__device__ __forceinline__ void ldsm4(uint32_t addr, uint32_t& r0, uint32_t& r1,
                                      uint32_t& r2, uint32_t& r3) {
    asm volatile("ldmatrix.sync.aligned.m8n8.x4.shared.b16 {%0,%1,%2,%3}, [%4];"
                 : "=r"(r0), "=r"(r1), "=r"(r2), "=r"(r3) : "r"(addr));
}

__device__ __forceinline__ void mma16(float* d,
                                      uint32_t a0, uint32_t a1, uint32_t a2, uint32_t a3,
                                      uint32_t b0, uint32_t b1) {
    asm volatile("mma.sync.aligned.m16n8k16.row.col.f32.f16.f16.f32 "
                 "{%0,%1,%2,%3}, {%4,%5,%6,%7}, {%8,%9}, {%0,%1,%2,%3};"
                 : "+f"(d[0]), "+f"(d[1]), "+f"(d[2]), "+f"(d[3])
                 : "r"(a0), "r"(a1), "r"(a2), "r"(a3), "r"(b0), "r"(b1));
}

__device__ __forceinline__ void zero_acc(float (&acc)[4][8][4]) {
#pragma unroll
    for (int i = 0; i < 4; ++i)
#pragma unroll
        for (int j = 0; j < 8; ++j)
#pragma unroll
            for (int q = 0; q < 4; ++q) acc[i][j][q] = 0.0f;
}

__device__ __forceinline__ void sth(char* smc, int buf, int row, int kh, __half v) {
    *(__half*)(smc + buf + row * 256 + ((((kh >> 3) ^ (row & 7))) << 4) + (kh & 7) * 2) = v;
}
__device__ __forceinline__ void sth2(char* smc, int buf, int row, int kh, __half2 v) {
    *(__half2*)(smc + buf + row * 256 + ((((kh >> 3) ^ (row & 7))) << 4) + (kh & 7) * 2) = v;
}

// 128x128x128 fp16 GEMM, 4 warps, 64x64 warp tiles, swizzled operands.
// tA[4], tB[4]: per-lane row-base byte addrs. K = 8 steps of k16.
// PREF: stage W[l+1]^T (global row-major [c][u], fp32) into B_WT as fp16.
template<bool PREF>
__device__ __forceinline__ void gemm128(const uint32_t* tA, const uint32_t* tB,
                                        float (&acc)[4][8][4],
                                        const float* __restrict__ wg,
                                        char* smc, int warp, int lane,
                                        uint32_t csel, uint32_t rl) {
    float4 ra[4], rb[4];
    int cbase = 0, uu = 0;
    if (PREF) {
        cbase = lane & 7;
        uu = warp * 32 + ((lane >> 3) << 3);   // 8 consecutive u per lane
#pragma unroll
        for (int r = 0; r < 4; ++r) {
            ra[r] = *(const float4*)(wg + (8 * r + cbase) * 128 + uu);
            rb[r] = *(const float4*)(wg + (8 * r + cbase) * 128 + uu + 4);
        }
    }
#pragma unroll
    for (int k = 0; k < 8; ++k) {
        const uint32_t cc = ((((uint32_t)k << 1) | csel) ^ rl) << 4;
        uint32_t A[4][4], B[4][4];
#pragma unroll
        for (int mt = 0; mt < 4; ++mt)
            ldsm4(tA[mt] + cc, A[mt][0], A[mt][1], A[mt][2], A[mt][3]);
#pragma unroll
        for (int nb = 0; nb < 4; ++nb)
            ldsm4(tB[nb] + cc, B[nb][0], B[nb][1], B[nb][2], B[nb][3]);
#pragma unroll
        for (int mt = 0; mt < 4; ++mt)
#pragma unroll
            for (int nt = 0; nt < 8; ++nt)
                mma16(acc[mt][nt], A[mt][0], A[mt][1], A[mt][2], A[mt][3],
                      B[nt >> 1][nt & 1], B[nt >> 1][(nt & 1) + 2]);
        if (PREF) {
#pragma unroll
            for (int h = 0; h < 2; ++h) {
                const int kk = 2 * k + h;
                const int c = 8 * kk + cbase;
                const int s = kk & 3;
                float4 v0 = ra[s], v1 = rb[s];
                sth(smc, B_WT, uu + 0, c, __float2half_rn(v0.x));
                sth(smc, B_WT, uu + 1, c, __float2half_rn(v0.y));
                sth(smc, B_WT, uu + 2, c, __float2half_rn(v0.z));
                sth(smc, B_WT, uu + 3, c, __float2half_rn(v0.w));
                sth(smc, B_WT, uu + 4, c, __float2half_rn(v1.x));
                sth(smc, B_WT, uu + 5, c, __float2half_rn(v1.y));
                sth(smc, B_WT, uu + 6, c, __float2half_rn(v1.z));
                sth(smc, B_WT, uu + 7, c, __float2half_rn(v1.w));
                if (kk + 4 < 16) {
                    ra[s] = *(const float4*)(wg + (8 * (kk + 4) + cbase) * 128 + uu);
                    rb[s] = *(const float4*)(wg + (8 * (kk + 4) + cbase) * 128 + uu + 4);
                }
            }
        }
    }
}

__global__ __launch_bounds__(NTH, 2)
void gcn_mma_kernel(const int* __restrict__ pdg,
                    const float* __restrict__ feat,
                    const float* __restrict__ adj,
                    const float* __restrict__ mask,
                    const float* __restrict__ emb,
                    const float* __restrict__ W_in,
                    const float* __restrict__ b_in,
                    const float* __restrict__ W_h,
                    const float* __restrict__ b_h,
                    const float* __restrict__ W_out,
                    const float* __restrict__ b_out,
                    float* __restrict__ out)
{
    extern __shared__ float smf[];
    char* smc = (char*)smf;
    const uint32_t SB = smem_u32(smf);

    const int b    = blockIdx.x;
    const int tid  = threadIdx.x;
    const int lane = tid & 31;
    const int warp = tid >> 5;          // 0..3

    const int m0 = (warp >> 1) * 64;    // 2 (m) x 2 (n) warps, tile 64x64
    const int n0 = (warp & 1) * 64;

    const int aRow      = (lane & 7) + ((lane >> 3) & 1) * 8;  // 0..15
    const uint32_t csel = (uint32_t)(lane >> 4);               // 0..1
    const uint32_t rl   = (uint32_t)(aRow & 7);

    const int er = lane >> 2;           // 0..7
    const int ec = (lane & 3) * 2;      // 0,2,4,6

    const float* adjb = adj + (size_t)b * 16384;

    // ================= staging =================
#pragma unroll
    for (int i = 0; i < 32; ++i) {      // adj -> ADJ fp16 swizzled
        int idx = i * 128 + tid;
        int row = idx >> 5, c4 = idx & 31;
        float4 v = *(const float4*)(adjb + row * 128 + c4 * 4);
        sth2(smc, B_ADJ, row, c4 * 4,     __floats2half2_rn(v.x, v.y));
        sth2(smc, B_ADJ, row, c4 * 4 + 2, __floats2half2_rn(v.z, v.w));
    }
    {                                   // W_h[0]^T -> WT, PREF-identical map
        int cb = lane & 7;
        int uu = warp * 32 + ((lane >> 3) << 3);
#pragma unroll
        for (int kk = 0; kk < 16; ++kk) {
            int c = 8 * kk + cb;
            float4 v0 = *(const float4*)(W_h + c * 128 + uu);
            float4 v1 = *(const float4*)(W_h + c * 128 + uu + 4);
            sth(smc, B_WT, uu + 0, c, __float2half_rn(v0.x));
            sth(smc, B_WT, uu + 1, c, __float2half_rn(v0.y));
            sth(smc, B_WT, uu + 2, c, __float2half_rn(v0.z));
            sth(smc, B_WT, uu + 3, c, __float2half_rn(v0.w));
            sth(smc, B_WT, uu + 4, c, __float2half_rn(v1.x));
            sth(smc, B_WT, uu + 5, c, __float2half_rn(v1.y));
            sth(smc, B_WT, uu + 6, c, __float2half_rn(v1.z));
            sth(smc, B_WT, uu + 7, c, __float2half_rn(v1.w));
        }
    }
    {                                   // x0 -> X0 (fp16, 32B rows, unswizzled)
        int p = tid;
        float4 f0 = *(const float4*)(feat + ((size_t)b * 128 + p) * 8);
        float4 f1 = *(const float4*)(feat + ((size_t)b * 128 + p) * 8 + 4);
        int pg = pdg[(size_t)b * 128 + p];
        float4 e0 = *(const float4*)(emb + pg * 8);
        float4 e1 = *(const float4*)(emb + pg * 8 + 4);
        __half2* d = (__half2*)(smc + B_X0 + p * 32);
        d[0] = __floats2half2_rn(f0.x, f0.y);
        d[1] = __floats2half2_rn(f0.z, f0.w);
        d[2] = __floats2half2_rn(f1.x, f1.y);
        d[3] = __floats2half2_rn(f1.z, f1.w);
        d[4] = __floats2half2_rn(e0.x, e0.y);
        d[5] = __floats2half2_rn(e0.z, e0.w);
        d[6] = __floats2half2_rn(e1.x, e1.y);
        d[7] = __floats2half2_rn(e1.z, e1.w);
    }
#pragma unroll
    for (int i = 0; i < 4; ++i) {       // W_in^T -> WINT (rows u, 16 halves)
        int idx = i * 128 + tid;
        int c = idx >> 5, u0 = (idx & 31) * 4;
        float4 wv = *(const float4*)(W_in + idx * 4);
        *(__half*)(smc + B_WINT + (u0 + 0) * 32 + c * 2) = __float2half_rn(wv.x);
        *(__half*)(smc + B_WINT + (u0 + 1) * 32 + c * 2) = __float2half_rn(wv.y);
        *(__half*)(smc + B_WINT + (u0 + 2) * 32 + c * 2) = __float2half_rn(wv.z);
        *(__half*)(smc + B_WINT + (u0 + 3) * 32 + c * 2) = __float2half_rn(wv.w);
    }
#pragma unroll
    for (int i = 0; i < 2; ++i) {       // b_h pre-scaled by 8^-(l+1)
        int idx = i * 128 + tid;
        if (idx < 192) {
            int l = idx >> 5;
            float s = exp2f(-3.0f * (float)(l + 1));
            float4 v = *(const float4*)(b_h + idx * 4);
            *(float4*)&smf[F_BIA + idx * 4] =
                make_float4(v.x * s, v.y * s, v.z * s, v.w * s);
        }
    }
    if (tid < 32) {                     // b_in
        *(float4*)&smf[F_BIN + tid * 4] = *(const float4*)(b_in + tid * 4);
    } else if (tid < 64) {              // mask
        int q = tid - 32;
        *(float4*)&smf[F_MSK + q * 4] = *(const float4*)(mask + (size_t)b * 128 + q * 4);
    } else if (tid < 96) {              // W_out
        int q = tid - 64;
        *(float4*)&smf[F_WO + q * 4] = *(const float4*)(W_out + q * 4);
    } else if (tid == 96) {
        smf[F_BOUT] = b_out[0];
    }
    __syncthreads();

    if (warp == 0) {                    // denom
        float s = smf[F_MSK + lane] + smf[F_MSK + lane + 32]
                + smf[F_MSK + lane + 64] + smf[F_MSK + lane + 96];
#pragma unroll
        for (int o = 16; o; o >>= 1) s += __shfl_down_sync(0xffffffffu, s, o);
        if (lane == 0) smf[F_RED + 7] = fmaxf(s, 1.0f);
    }

    float acc[4][8][4];

    // per-lane tile row-base addresses for the swizzled buffers
    uint32_t tACT[4], tADJ[4], tWT[4], nACT[4];
#pragma unroll
    for (int t = 0; t < 4; ++t) {
        uint32_t rbm = (uint32_t)(m0 + t * 16 + aRow) * 256u;
        uint32_t rbn = (uint32_t)(n0 + t * 16 + aRow) * 256u;
        tADJ[t] = SB + B_ADJ + rbm;
        tACT[t] = SB + B_ACT + rbm;
        tWT[t]  = SB + B_WT  + rbm;
        nACT[t] = SB + B_ACT + rbn;
    }

    // ================= input GEMM: X = x0 @ W_in + b_in (K=16, 1 step) =========
    zero_acc(acc);
    {
        uint32_t A4[4][4], B4[4][4];
#pragma unroll
        for (int mt = 0; mt < 4; ++mt)
            ldsm4(SB + B_X0 + (uint32_t)(m0 + mt * 16 + aRow) * 32u + csel * 16u,
                  A4[mt][0], A4[mt][1], A4[mt][2], A4[mt][3]);
#pragma unroll
        for (int nb = 0; nb < 4; ++nb)
            ldsm4(SB + B_WINT + (uint32_t)(n0 + nb * 16 + aRow) * 32u + csel * 16u,
                  B4[nb][0], B4[nb][1], B4[nb][2], B4[nb][3]);
#pragma unroll
        for (int mt = 0; mt < 4; ++mt)
#pragma unroll
            for (int nt = 0; nt < 8; ++nt)
                mma16(acc[mt][nt], A4[mt][0], A4[mt][1], A4[mt][2], A4[mt][3],
                      B4[nt >> 1][nt & 1], B4[nt >> 1][(nt & 1) + 2]);
    }
    // epi: + b_in, store X fp16 (rows p, kh = u) into ACT
#pragma unroll
    for (int mt = 0; mt < 4; ++mt)
#pragma unroll
        for (int nt = 0; nt < 8; ++nt) {
            int p0 = m0 + mt * 16 + er;
            int u0 = n0 + nt * 8 + ec;
            float bi0 = smf[F_BIN + u0], bi1 = smf[F_BIN + u0 + 1];
            sth2(smc, B_ACT, p0,     u0, __floats2half2_rn(acc[mt][nt][0] + bi0,
                                                           acc[mt][nt][1] + bi1));
            sth2(smc, B_ACT, p0 + 8, u0, __floats2half2_rn(acc[mt][nt][2] + bi0,
                                                           acc[mt][nt][3] + bi1));
        }
    __syncthreads();

    // ================= hidden layers =================
#pragma unroll 1
    for (int l = 0; l < NHID; ++l) {
        // GEMM1 (flipped): Y^T[u][p] : A = WT (rows u), B^T = X (rows p, kh=u)
        zero_acc(acc);
        gemm128<false>(tWT, nACT, acc, nullptr, smc, warp, lane, csel, rl);
        __syncthreads();
        // epi1: Ytilde = relu(acc*0.125 + b*8^-(l+1)); store Y^T (rows u, kh=p)
#pragma unroll
        for (int mt = 0; mt < 4; ++mt) {
            int u0 = m0 + mt * 16 + er;
            float bi  = smf[F_BIA + l * 128 + u0];
            float bi8 = smf[F_BIA + l * 128 + u0 + 8];
#pragma unroll
            for (int nt = 0; nt < 8; ++nt) {
                int p0 = n0 + nt * 8 + ec;
                sth2(smc, B_ACT, u0, p0,
                     __floats2half2_rn(fmaxf(acc[mt][nt][0] * 0.125f + bi, 0.0f),
                                       fmaxf(acc[mt][nt][1] * 0.125f + bi, 0.0f)));
                sth2(smc, B_ACT, u0 + 8, p0,
                     __floats2half2_rn(fmaxf(acc[mt][nt][2] * 0.125f + bi8, 0.0f),
                                       fmaxf(acc[mt][nt][3] * 0.125f + bi8, 0.0f)));
            }
        }
        __syncthreads();

        // GEMM2: X'[p][u] : A = ADJ (rows p), B^T = Y^T (rows u, kh=p)
        zero_acc(acc);
        if (l + 1 < NHID)
            gemm128<true>(tADJ, nACT, acc, W_h + (size_t)(l + 1) * 16384,
                          smc, warp, lane, csel, rl);
        else
            gemm128<false>(tADJ, nACT, acc, nullptr, smc, warp, lane, csel, rl);
        __syncthreads();
        // epi2: store X' fp16 (rows p, kh = u) — already carries scale 8^-(l+1)
#pragma unroll
        for (int mt = 0; mt < 4; ++mt)
#pragma unroll
            for (int nt = 0; nt < 8; ++nt) {
                int p0 = m0 + mt * 16 + er;
                int u0 = n0 + nt * 8 + ec;
                sth2(smc, B_ACT, p0,     u0,
                     __floats2half2_rn(acc[mt][nt][0], acc[mt][nt][1]));
                sth2(smc, B_ACT, p0 + 8, u0,
                     __floats2half2_rn(acc[mt][nt][2], acc[mt][nt][3]));
            }
        __syncthreads();
    }

    // ================= masked mean pool + output projection =================
    {
        int u = tid;
        float s = 0.0f;
#pragma unroll 8
        for (int p = 0; p < 128; ++p) {
            __half hv = *(const __half*)(smc + B_ACT + p * 256
                         + ((((u >> 3) ^ (p & 7))) << 4) + (u & 7) * 2);
            s += __half2float(hv) * smf[F_MSK + p];
        }
        // undo scale 8^-6 = 2^-18 exactly
        float pooled = s * 262144.0f / smf[F_RED + 7];
        float v = pooled * smf[F_WO + u];
#pragma unroll
        for (int o = 16; o; o >>= 1) v += __shfl_down_sync(0xffffffffu, v, o);
        if (lane == 0) smf[F_RED + warp] = v;
    }
    __syncthreads();
    if (tid == 0)
        out[b] = smf[F_RED + 0] + smf[F_RED + 1] + smf[F_RED + 2] + smf[F_RED + 3]
               + smf[F_BOUT];
}

extern "C" void kernel_launch(void* const* d_in, const int* in_sizes, int n_in,
                              void* d_out, int out_size)
{
    const int*   pdg   = (const int*)  d_in[0];
    const float* feat  = (const float*)d_in[1];
    const float* adjp  = (const float*)d_in[2];
    const float* maskp = (const float*)d_in[3];
    const float* emb   = (const float*)d_in[4];
    const float* W_in  = (const float*)d_in[5];
    const float* b_in  = (const float*)d_in[6];
    const float* W_h   = (const float*)d_in[7];
    const float* b_h   = (const float*)d_in[8];
    const float* W_out = (const float*)d_in[9];
    const float* b_out = (const float*)d_in[10];
    float* out = (float*)d_out;

    const int B = in_sizes[0] / 128;

    cudaFuncSetAttribute(gcn_mma_kernel,
                         cudaFuncAttributeMaxDynamicSharedMemorySize, SMEM_BYTES);
    gcn_mma_kernel<<<B, NTH, SMEM_BYTES>>>(
        pdg, feat, adjp, maskp, emb, W_in, b_in, W_h, b_h, W_out, b_out, out);
}

// round 15
// speedup vs baseline: 1.0675x; 1.0675x over previous
#include <cuda_runtime.h>
#include <cuda_fp16.h>
#include <cstdint>

#define NTH  256
#define NHID 6

// fp16 operands, 128x128, rows of 128 halves = 256B, XOR-swizzled:
//   byte(row, kh) = row*256 + (((kh>>3) ^ (row&7))<<4) + (kh&7)*2
#define B_ADJ   0
#define B_ACT   32768
#define B_WT    65536
#define B_X0    98304       // 128 rows x 32B (16 halves), unswizzled
#define B_WINT  102400      // 128 rows x 32B
// float-indexed misc
#define F_BIN   26624       // 128 (b_in; reused as VF after input GEMM)
#define F_BIA   26752       // 768 (pre-scaled by 8^-(l+1))
#define F_MSK   27520       // 128
#define F_WO    27648       // 128
#define F_PART  27776       // 256 (v halves)
#define F_RED   28032       // 8 (per-warp output partials)
#define F_BOUT  28040
#define F_DEN   28041
#define SMEM_BYTES 112192

__device__ __forceinline__ uint32_t smem_u32(const void* p) {
    uint32_t a;
    asm("{ .reg .u64 t; cvta.to.shared.u64 t, %1; cvt.u32.u64 %0, t; }" : "=r"(a) : "l"(p));
    return a;
}

__device__ __forceinline__ void ldsm4(uint32_t addr, uint32_t& r0, uint32_t& r1,
                                      uint32_t& r2, uint32_t& r3) {
    asm volatile("ldmatrix.sync.aligned.m8n8.x4.shared.b16 {%0,%1,%2,%3}, [%4];"
                 : "=r"(r0), "=r"(r1), "=r"(r2), "=r"(r3) : "r"(addr));
}

__device__ __forceinline__ void mma16(float* d,
                                      uint32_t a0, uint32_t a1, uint32_t a2, uint32_t a3,
                                      uint32_t b0, uint32_t b1) {
    asm volatile("mma.sync.aligned.m16n8k16.row.col.f32.f16.f16.f32 "
                 "{%0,%1,%2,%3}, {%4,%5,%6,%7}, {%8,%9}, {%0,%1,%2,%3};"
                 : "+f"(d[0]), "+f"(d[1]), "+f"(d[2]), "+f"(d[3])
                 : "r"(a0), "r"(a1), "r"(a2), "r"(a3), "r"(b0), "r"(b1));
}

__device__ __forceinline__ void zero_acc(float (&acc)[4][4][4]) {
#pragma unroll
    for (int i = 0; i < 4; ++i)
#pragma unroll
        for (int j = 0; j < 4; ++j)
#pragma unroll
            for (int q = 0; q < 4; ++q) acc[i][j][q] = 0.0f;
}

__device__ __forceinline__ void sth(char* smc, int buf, int row, int kh, __half v) {
    *(__half*)(smc + buf + row * 256 + ((((kh >> 3) ^ (row & 7))) << 4) + (kh & 7) * 2) = v;
}
__device__ __forceinline__ void sth2(char* smc, int buf, int row, int kh, __half2 v) {
    *(__half2*)(smc + buf + row * 256 + ((((kh >> 3) ^ (row & 7))) << 4) + (kh & 7) * 2) = v;
}

// 128x128x128 fp16 GEMM, 8 warps, 64x32 warp tiles, swizzled operands.
// PREF: stage W[l+1]^T (global row-major [c][u], fp32) into B_WT as fp16.
template<bool PREF>
__device__ __forceinline__ void gemm128(const uint32_t* tA, const uint32_t* tB,
                                        float (&acc)[4][4][4],
                                        const float* __restrict__ wg,
                                        char* smc, int warp, int lane,
                                        uint32_t csel, uint32_t rl) {
    float4 ring[4];
    int cbase = 0, ubase = 0;
    if (PREF) {
        cbase = lane & 7;
        ubase = warp * 16 + ((lane >> 3) << 2);
#pragma unroll
        for (int r = 0; r < 4; ++r)
            ring[r] = *(const float4*)(wg + (8 * r + cbase) * 128 + ubase);
    }
#pragma unroll
    for (int k = 0; k < 8; ++k) {
        const uint32_t cc = ((((uint32_t)k << 1) | csel) ^ rl) << 4;
        uint32_t A[4][4], B[2][4];
#pragma unroll
        for (int mt = 0; mt < 4; ++mt)
            ldsm4(tA[mt] + cc, A[mt][0], A[mt][1], A[mt][2], A[mt][3]);
#pragma unroll
        for (int nb = 0; nb < 2; ++nb)
            ldsm4(tB[nb] + cc, B[nb][0], B[nb][1], B[nb][2], B[nb][3]);
#pragma unroll
        for (int mt = 0; mt < 4; ++mt)
#pragma unroll
            for (int nt = 0; nt < 4; ++nt)
                mma16(acc[mt][nt], A[mt][0], A[mt][1], A[mt][2], A[mt][3],
                      B[nt >> 1][nt & 1], B[nt >> 1][(nt & 1) + 2]);
        if (PREF) {
#pragma unroll
            for (int h = 0; h < 2; ++h) {
                const int kk = 2 * k + h;
                const int c = 8 * kk + cbase;
                float4 v = ring[kk & 3];
                sth(smc, B_WT, ubase + 0, c, __float2half_rn(v.x));
                sth(smc, B_WT, ubase + 1, c, __float2half_rn(v.y));
                sth(smc, B_WT, ubase + 2, c, __float2half_rn(v.z));
                sth(smc, B_WT, ubase + 3, c, __float2half_rn(v.w));
                if (kk + 4 < 16)
                    ring[kk & 3] = *(const float4*)(wg + (8 * (kk + 4) + cbase) * 128 + ubase);
            }
        }
    }
}

__global__ __launch_bounds__(NTH, 2)
void gcn_mma_kernel(const int* __restrict__ pdg,
                    const float* __restrict__ feat,
                    const float* __restrict__ adj,
                    const float* __restrict__ mask,
                    const float* __restrict__ emb,
                    const float* __restrict__ W_in,
                    const float* __restrict__ b_in,
                    const float* __restrict__ W_h,
                    const float* __restrict__ b_h,
                    const float* __restrict__ W_out,
                    const float* __restrict__ b_out,
                    float* __restrict__ out)
{
    extern __shared__ float smf[];
    char* smc = (char*)smf;
    const uint32_t SB = smem_u32(smf);

    const int b    = blockIdx.x;
    const int tid  = threadIdx.x;
    const int lane = tid & 31;
    const int warp = tid >> 5;          // 0..7

    const int m0 = (warp >> 2) * 64;    // 2 (m) x 4 (n) warps, tile 64x32
    const int n0 = (warp & 3) * 32;

    const int aRow      = (lane & 7) + ((lane >> 3) & 1) * 8;  // 0..15
    const uint32_t csel = (uint32_t)(lane >> 4);               // 0..1
    const uint32_t rl   = (uint32_t)(aRow & 7);

    const int er = lane >> 2;           // 0..7
    const int ec = (lane & 3) * 2;      // 0,2,4,6

    const float* adjb = adj + (size_t)b * 16384;

    // ================= staging =================
#pragma unroll
    for (int i = 0; i < 16; ++i) {      // adj -> ADJ fp16 swizzled
        int idx = i * 256 + tid;
        int row = idx >> 5, c4 = idx & 31;
        float4 v = *(const float4*)(adjb + row * 128 + c4 * 4);
        sth2(smc, B_ADJ, row, c4 * 4,     __floats2half2_rn(v.x, v.y));
        sth2(smc, B_ADJ, row, c4 * 4 + 2, __floats2half2_rn(v.z, v.w));
    }
    {                                   // W_h[0]^T -> WT, PREF-identical map
        int cb = lane & 7;
        int u0 = warp * 16 + ((lane >> 3) << 2);
#pragma unroll
        for (int kk = 0; kk < 16; ++kk) {
            int c = 8 * kk + cb;
            float4 v = *(const float4*)(W_h + c * 128 + u0);
            sth(smc, B_WT, u0 + 0, c, __float2half_rn(v.x));
            sth(smc, B_WT, u0 + 1, c, __float2half_rn(v.y));
            sth(smc, B_WT, u0 + 2, c, __float2half_rn(v.z));
            sth(smc, B_WT, u0 + 3, c, __float2half_rn(v.w));
        }
    }
    if (tid < 128) {                    // x0 -> X0 (fp16, 32B rows, unswizzled)
        int p = tid;
        float4 f0 = *(const float4*)(feat + ((size_t)b * 128 + p) * 8);
        float4 f1 = *(const float4*)(feat + ((size_t)b * 128 + p) * 8 + 4);
        int pg = pdg[(size_t)b * 128 + p];
        float4 e0 = *(const float4*)(emb + pg * 8);
        float4 e1 = *(const float4*)(emb + pg * 8 + 4);
        __half2* d = (__half2*)(smc + B_X0 + p * 32);
        d[0] = __floats2half2_rn(f0.x, f0.y);
        d[1] = __floats2half2_rn(f0.z, f0.w);
        d[2] = __floats2half2_rn(f1.x, f1.y);
        d[3] = __floats2half2_rn(f1.z, f1.w);
        d[4] = __floats2half2_rn(e0.x, e0.y);
        d[5] = __floats2half2_rn(e0.z, e0.w);
        d[6] = __floats2half2_rn(e1.x, e1.y);
        d[7] = __floats2half2_rn(e1.z, e1.w);
    }
#pragma unroll
    for (int i = 0; i < 2; ++i) {       // W_in^T -> WINT (rows u, 16 halves)
        int idx = i * 256 + tid;
        int c = idx >> 5, u0 = (idx & 31) * 4;
        float4 wv = *(const float4*)(W_in + idx * 4);
        *(__half*)(smc + B_WINT + (u0 + 0) * 32 + c * 2) = __float2half_rn(wv.x);
        *(__half*)(smc + B_WINT + (u0 + 1) * 32 + c * 2) = __float2half_rn(wv.y);
        *(__half*)(smc + B_WINT + (u0 + 2) * 32 + c * 2) = __float2half_rn(wv.z);
        *(__half*)(smc + B_WINT + (u0 + 3) * 32 + c * 2) = __float2half_rn(wv.w);
    }
    if (tid < 192) {                    // b_h pre-scaled by 8^-(l+1)
        int l = tid >> 5;
        float s = exp2f(-3.0f * (float)(l + 1));
        float4 v = *(const float4*)(b_h + tid * 4);
        *(float4*)&smf[F_BIA + tid * 4] =
            make_float4(v.x * s, v.y * s, v.z * s, v.w * s);
    }
    if (tid < 32) {                     // b_in
        *(float4*)&smf[F_BIN + tid * 4] = *(const float4*)(b_in + tid * 4);
    } else if (tid < 64) {              // mask
        int q = tid - 32;
        *(float4*)&smf[F_MSK + q * 4] = *(const float4*)(mask + (size_t)b * 128 + q * 4);
    } else if (tid < 96) {              // W_out
        int q = tid - 64;
        *(float4*)&smf[F_WO + q * 4] = *(const float4*)(W_out + q * 4);
    } else if (tid == 96) {
        smf[F_BOUT] = b_out[0];
    }
    __syncthreads();

    if (warp == 0) {                    // denom -> F_DEN
        float s = smf[F_MSK + lane] + smf[F_MSK + lane + 32]
                + smf[F_MSK + lane + 64] + smf[F_MSK + lane + 96];
#pragma unroll
        for (int o = 16; o; o >>= 1) s += __shfl_down_sync(0xffffffffu, s, o);
        if (lane == 0) smf[F_DEN] = fmaxf(s, 1.0f);
    }

    // v = mask^T adj (column sums of masked adj), halves in F_PART
    {
        int n = tid & 127, h = tid >> 7;
        float s = 0.0f;
#pragma unroll 8
        for (int i = 0; i < 64; ++i) {
            int p = h * 64 + i;
            __half hv = *(const __half*)(smc + B_ADJ + p * 256
                         + ((((n >> 3) ^ (p & 7))) << 4) + (n & 7) * 2);
            s += __half2float(hv) * smf[F_MSK + p];
        }
        smf[F_PART + h * 128 + n] = s;
    }

    float acc[4][4][4];

    uint32_t tACT[4], tADJ[4], tWT[4];
#pragma unroll
    for (int mt = 0; mt < 4; ++mt) {
        uint32_t rb = (uint32_t)(m0 + mt * 16 + aRow) * 256u;
        tADJ[mt] = SB + B_ADJ + rb;
        tACT[mt] = SB + B_ACT + rb;
        tWT[mt]  = SB + B_WT  + rb;
    }
    uint32_t nACT[2];
#pragma unroll
    for (int nb = 0; nb < 2; ++nb) {
        uint32_t rb = (uint32_t)(n0 + nb * 16 + aRow) * 256u;
        nACT[nb] = SB + B_ACT + rb;
    }

    // ================= input GEMM: X = x0 @ W_in + b_in (K=16, 1 step) =========
    zero_acc(acc);
    {
        uint32_t A4[4][4], B4[2][4];
#pragma unroll
        for (int mt = 0; mt < 4; ++mt)
            ldsm4(SB + B_X0 + (uint32_t)(m0 + mt * 16 + aRow) * 32u + csel * 16u,
                  A4[mt][0], A4[mt][1], A4[mt][2], A4[mt][3]);
#pragma unroll
        for (int nb = 0; nb < 2; ++nb)
            ldsm4(SB + B_WINT + (uint32_t)(n0 + nb * 16 + aRow) * 32u + csel * 16u,
                  B4[nb][0], B4[nb][1], B4[nb][2], B4[nb][3]);
#pragma unroll
        for (int mt = 0; mt < 4; ++mt)
#pragma unroll
            for (int nt = 0; nt < 4; ++nt)
                mma16(acc[mt][nt], A4[mt][0], A4[mt][1], A4[mt][2], A4[mt][3],
                      B4[nt >> 1][nt & 1], B4[nt >> 1][(nt & 1) + 2]);
    }
#pragma unroll
    for (int mt = 0; mt < 4; ++mt)
#pragma unroll
        for (int nt = 0; nt < 4; ++nt) {
            int p0 = m0 + mt * 16 + er;
            int u0 = n0 + nt * 8 + ec;
            float bi0 = smf[F_BIN + u0], bi1 = smf[F_BIN + u0 + 1];
            sth2(smc, B_ACT, p0,     u0, __floats2half2_rn(acc[mt][nt][0] + bi0,
                                                           acc[mt][nt][1] + bi1));
            sth2(smc, B_ACT, p0 + 8, u0, __floats2half2_rn(acc[mt][nt][2] + bi0,
                                                           acc[mt][nt][3] + bi1));
        }
    __syncthreads();

    // ================= hidden layers 0..4 (full) =================
#pragma unroll 1
    for (int l = 0; l < NHID - 1; ++l) {
        // GEMM1 (flipped): Y^T[u][p] : A = WT (rows u), B^T = X (rows p, kh=u)
        zero_acc(acc);
        gemm128<false>(tWT, nACT, acc, nullptr, smc, warp, lane, csel, rl);
        __syncthreads();
        // epi1: Ytilde = relu(acc*0.125 + b*8^-(l+1)); store Y^T (rows u, kh=p)
#pragma unroll
        for (int mt = 0; mt < 4; ++mt) {
            int u0 = m0 + mt * 16 + er;
            float bi  = smf[F_BIA + l * 128 + u0];
            float bi8 = smf[F_BIA + l * 128 + u0 + 8];
#pragma unroll
            for (int nt = 0; nt < 4; ++nt) {
                int p0 = n0 + nt * 8 + ec;
                sth2(smc, B_ACT, u0, p0,
                     __floats2half2_rn(fmaxf(acc[mt][nt][0] * 0.125f + bi, 0.0f),
                                       fmaxf(acc[mt][nt][1] * 0.125f + bi, 0.0f)));
                sth2(smc, B_ACT, u0 + 8, p0,
                     __floats2half2_rn(fmaxf(acc[mt][nt][2] * 0.125f + bi8, 0.0f),
                                       fmaxf(acc[mt][nt][3] * 0.125f + bi8, 0.0f)));
            }
        }
        __syncthreads();

        // GEMM2: X'[p][u] : A = ADJ (rows p), B^T = Y^T (rows u, kh=p)
        // (+ prefetch W_h[l+1] into WT; l+1 <= 5 always here)
        zero_acc(acc);
        gemm128<true>(tADJ, nACT, acc, W_h + (size_t)(l + 1) * 16384,
                      smc, warp, lane, csel, rl);
        __syncthreads();
#pragma unroll
        for (int mt = 0; mt < 4; ++mt)
#pragma unroll
            for (int nt = 0; nt < 4; ++nt) {
                int p0 = m0 + mt * 16 + er;
                int u0 = n0 + nt * 8 + ec;
                sth2(smc, B_ACT, p0,     u0,
                     __floats2half2_rn(acc[mt][nt][0], acc[mt][nt][1]));
                sth2(smc, B_ACT, p0 + 8, u0,
                     __floats2half2_rn(acc[mt][nt][2], acc[mt][nt][3]));
            }
        __syncthreads();
    }

    // ================= layer 5: dense GEMM + relu only =================
    zero_acc(acc);
    gemm128<false>(tWT, nACT, acc, nullptr, smc, warp, lane, csel, rl);
    __syncthreads();
#pragma unroll
    for (int mt = 0; mt < 4; ++mt) {
        int u0 = m0 + mt * 16 + er;
        float bi  = smf[F_BIA + 5 * 128 + u0];
        float bi8 = smf[F_BIA + 5 * 128 + u0 + 8];
#pragma unroll
        for (int nt = 0; nt < 4; ++nt) {
            int p0 = n0 + nt * 8 + ec;
            sth2(smc, B_ACT, u0, p0,
                 __floats2half2_rn(fmaxf(acc[mt][nt][0] * 0.125f + bi, 0.0f),
                                   fmaxf(acc[mt][nt][1] * 0.125f + bi, 0.0f)));
            sth2(smc, B_ACT, u0 + 8, p0,
                 __floats2half2_rn(fmaxf(acc[mt][nt][2] * 0.125f + bi8, 0.0f),
                                   fmaxf(acc[mt][nt][3] * 0.125f + bi8, 0.0f)));
        }
    }
    __syncthreads();

    // VF[p] = v[p] (combine halves) into F_BIN (b_in dead)
    if (tid < 128)
        smf[F_BIN + tid] = smf[F_PART + tid] + smf[F_PART + 128 + tid];
    __syncthreads();

    // ================= pooled = v^T Ytilde6 * 2^18 / denom; out = pooled@W_out ==
    {
        int u = tid >> 1, h = tid & 1;
        float s = 0.0f;
#pragma unroll 8
        for (int j = 0; j < 32; ++j) {
            int p = h * 64 + j * 2;
            __half2 hv = *(const __half2*)(smc + B_ACT + u * 256
                          + ((((p >> 3) ^ (u & 7))) << 4) + (p & 7) * 2);
            float2 f = __half22float2(hv);
            s += f.x * smf[F_BIN + p] + f.y * smf[F_BIN + p + 1];
        }
        s += __shfl_xor_sync(0xffffffffu, s, 1);
        float val = (lane & 1) ? 0.0f
                  : s * 262144.0f / smf[F_DEN] * smf[F_WO + u];
#pragma unroll
        for (int o = 16; o; o >>= 1) val += __shfl_down_sync(0xffffffffu, val, o);
        if (lane == 0) smf[F_RED + warp] = val;
    }
    __syncthreads();
    if (tid == 0) {
        float r = 0.0f;
#pragma unroll
        for (int w = 0; w < 8; ++w) r += smf[F_RED + w];
        out[b] = r + smf[F_BOUT];
    }
}

extern "C" void kernel_launch(void* const* d_in, const int* in_sizes, int n_in,
                              void* d_out, int out_size)
{
    const int*   pdg   = (const int*)  d_in[0];
    const float* feat  = (const float*)d_in[1];
    const float* adjp  = (const float*)d_in[2];
    const float* maskp = (const float*)d_in[3];
    const float* emb   = (const float*)d_in[4];
    const float* W_in  = (const float*)d_in[5];
    const float* b_in  = (const float*)d_in[6];
    const float* W_h   = (const float*)d_in[7];
    const float* b_h   = (const float*)d_in[8];
    const float* W_out = (const float*)d_in[9];
    const float* b_out = (const float*)d_in[10];
    float* out = (float*)d_out;

    const int B = in_sizes[0] / 128;

    cudaFuncSetAttribute(gcn_mma_kernel,
                         cudaFuncAttributeMaxDynamicSharedMemorySize, SMEM_BYTES);
    gcn_mma_kernel<<<B, NTH, SMEM_BYTES>>>(
        pdg, feat, adjp, maskp, emb, W_in, b_in, W_h, b_h, W_out, b_out, out);
}

// round 16
// speedup vs baseline: 1.0686x; 1.0010x over previous
#include <cuda_runtime.h>
#include <cuda_fp16.h>
#include <cstdint>

#define NTH  256
#define NHID 6

// fp16 operands, 128x128, rows of 128 halves = 256B, XOR-swizzled:
//   byte(row, kh) = row*256 + (((kh>>3) ^ (row&7))<<4) + (kh&7)*2
#define B_ADJ   0
#define B_ACT   32768
#define B_WT    65536
#define B_X0    98304       // 128 rows x 32B (16 halves), unswizzled
#define B_WINT  102400      // 128 rows x 32B
// float-indexed misc
#define F_BIN   26624       // 128 (b_in; reused as VF after input GEMM)
#define F_BIA   26752       // 768 (pre-scaled by 8^-(l+1))
#define F_MSK   27520       // 128
#define F_WO    27648       // 128
#define F_PART  27776       // 256 (v halves)
#define F_RED   28032       // 8 (per-warp output partials)
#define F_BOUT  28040
#define F_DEN   28041
#define SMEM_BYTES 112192

__device__ __forceinline__ uint32_t smem_u32(const void* p) {
    uint32_t a;
    asm("{ .reg .u64 t; cvta.to.shared.u64 t, %1; cvt.u32.u64 %0, t; }" : "=r"(a) : "l"(p));
    return a;
}

__device__ __forceinline__ void ldsm4(uint32_t addr, uint32_t& r0, uint32_t& r1,
                                      uint32_t& r2, uint32_t& r3) {
    asm volatile("ldmatrix.sync.aligned.m8n8.x4.shared.b16 {%0,%1,%2,%3}, [%4];"
                 : "=r"(r0), "=r"(r1), "=r"(r2), "=r"(r3) : "r"(addr));
}

__device__ __forceinline__ void mma16(float* d,
                                      uint32_t a0, uint32_t a1, uint32_t a2, uint32_t a3,
                                      uint32_t b0, uint32_t b1) {
    asm volatile("mma.sync.aligned.m16n8k16.row.col.f32.f16.f16.f32 "
                 "{%0,%1,%2,%3}, {%4,%5,%6,%7}, {%8,%9}, {%0,%1,%2,%3};"
                 : "+f"(d[0]), "+f"(d[1]), "+f"(d[2]), "+f"(d[3])
                 : "r"(a0), "r"(a1), "r"(a2), "r"(a3), "r"(b0), "r"(b1));
}

// zero-accumulator form: d = a*b + 0 (no MOV-zeroing of acc needed)
__device__ __forceinline__ void mma16z(float* d,
                                       uint32_t a0, uint32_t a1, uint32_t a2, uint32_t a3,
                                       uint32_t b0, uint32_t b1) {
    asm volatile("mma.sync.aligned.m16n8k16.row.col.f32.f16.f16.f32 "
                 "{%0,%1,%2,%3}, {%4,%5,%6,%7}, {%8,%9}, {%10,%10,%10,%10};"
                 : "=f"(d[0]), "=f"(d[1]), "=f"(d[2]), "=f"(d[3])
                 : "r"(a0), "r"(a1), "r"(a2), "r"(a3), "r"(b0), "r"(b1),
                   "f"(0.0f));
}

__device__ __forceinline__ void sth(char* smc, int buf, int row, int kh, __half v) {
    *(__half*)(smc + buf + row * 256 + ((((kh >> 3) ^ (row & 7))) << 4) + (kh & 7) * 2) = v;
}
__device__ __forceinline__ void sth2(char* smc, int buf, int row, int kh, __half2 v) {
    *(__half2*)(smc + buf + row * 256 + ((((kh >> 3) ^ (row & 7))) << 4) + (kh & 7) * 2) = v;
}

// 128x128x128 fp16 GEMM, 8 warps, 64x32 warp tiles, swizzled operands.
// First k-step writes acc via zero-C mma (acc enters uninitialized).
// PREF: stage W[l+1]^T (global row-major [c][u], fp32) into B_WT as fp16.
template<bool PREF>
__device__ __forceinline__ void gemm128(const uint32_t* tA, const uint32_t* tB,
                                        float (&acc)[4][4][4],
                                        const float* __restrict__ wg,
                                        char* smc, int warp, int lane,
                                        uint32_t csel, uint32_t rl) {
    float4 ring[4];
    int cbase = 0, ubase = 0;
    if (PREF) {
        cbase = lane & 7;
        ubase = warp * 16 + ((lane >> 3) << 2);
#pragma unroll
        for (int r = 0; r < 4; ++r)
            ring[r] = *(const float4*)(wg + (8 * r + cbase) * 128 + ubase);
    }
#pragma unroll
    for (int k = 0; k < 8; ++k) {
        const uint32_t cc = ((((uint32_t)k << 1) | csel) ^ rl) << 4;
        uint32_t A[4][4], B[2][4];
#pragma unroll
        for (int mt = 0; mt < 4; ++mt)
            ldsm4(tA[mt] + cc, A[mt][0], A[mt][1], A[mt][2], A[mt][3]);
#pragma unroll
        for (int nb = 0; nb < 2; ++nb)
            ldsm4(tB[nb] + cc, B[nb][0], B[nb][1], B[nb][2], B[nb][3]);
#pragma unroll
        for (int mt = 0; mt < 4; ++mt)
#pragma unroll
            for (int nt = 0; nt < 4; ++nt) {
                if (k == 0)
                    mma16z(acc[mt][nt], A[mt][0], A[mt][1], A[mt][2], A[mt][3],
                           B[nt >> 1][nt & 1], B[nt >> 1][(nt & 1) + 2]);
                else
                    mma16(acc[mt][nt], A[mt][0], A[mt][1], A[mt][2], A[mt][3],
                          B[nt >> 1][nt & 1], B[nt >> 1][(nt & 1) + 2]);
            }
        if (PREF) {
#pragma unroll
            for (int h = 0; h < 2; ++h) {
                const int kk = 2 * k + h;
                const int c = 8 * kk + cbase;
                float4 v = ring[kk & 3];
                sth(smc, B_WT, ubase + 0, c, __float2half_rn(v.x));
                sth(smc, B_WT, ubase + 1, c, __float2half_rn(v.y));
                sth(smc, B_WT, ubase + 2, c, __float2half_rn(v.z));
                sth(smc, B_WT, ubase + 3, c, __float2half_rn(v.w));
                if (kk + 4 < 16)
                    ring[kk & 3] = *(const float4*)(wg + (8 * (kk + 4) + cbase) * 128 + ubase);
            }
        }
    }
}

__global__ __launch_bounds__(NTH, 2)
void gcn_mma_kernel(const int* __restrict__ pdg,
                    const float* __restrict__ feat,
                    const float* __restrict__ adj,
                    const float* __restrict__ mask,
                    const float* __restrict__ emb,
                    const float* __restrict__ W_in,
                    const float* __restrict__ b_in,
                    const float* __restrict__ W_h,
                    const float* __restrict__ b_h,
                    const float* __restrict__ W_out,
                    const float* __restrict__ b_out,
                    float* __restrict__ out)
{
    extern __shared__ float smf[];
    char* smc = (char*)smf;
    const uint32_t SB = smem_u32(smf);

    const int b    = blockIdx.x;
    const int tid  = threadIdx.x;
    const int lane = tid & 31;
    const int warp = tid >> 5;          // 0..7

    const int m0 = (warp >> 2) * 64;    // 2 (m) x 4 (n) warps, tile 64x32
    const int n0 = (warp & 3) * 32;

    const int aRow      = (lane & 7) + ((lane >> 3) & 1) * 8;  // 0..15
    const uint32_t csel = (uint32_t)(lane >> 4);               // 0..1
    const uint32_t rl   = (uint32_t)(aRow & 7);

    const int er = lane >> 2;           // 0..7
    const int ec = (lane & 3) * 2;      // 0,2,4,6

    // hoisted epilogue address constants (shared by input-epi, epi1, epi2):
    //   addr(mt, nt, row+0) = ebase + mt*4096 + ch4[nt]
    //   addr(mt, nt, row+8) = ebase + mt*4096 + ch4[nt] + 2048
    const int ebase = B_ACT + (m0 + er) * 256 + ec * 2;
    int ch4[4];
#pragma unroll
    for (int nt = 0; nt < 4; ++nt)
        ch4[nt] = ((((n0 >> 3) + nt) ^ er) << 4);

    const float* adjb = adj + (size_t)b * 16384;

    // ================= staging =================
#pragma unroll
    for (int i = 0; i < 16; ++i) {      // adj -> ADJ fp16 swizzled
        int idx = i * 256 + tid;
        int row = idx >> 5, c4 = idx & 31;
        float4 v = *(const float4*)(adjb + row * 128 + c4 * 4);
        sth2(smc, B_ADJ, row, c4 * 4,     __floats2half2_rn(v.x, v.y));
        sth2(smc, B_ADJ, row, c4 * 4 + 2, __floats2half2_rn(v.z, v.w));
    }
    {                                   // W_h[0]^T -> WT, PREF-identical map
        int cb = lane & 7;
        int u0 = warp * 16 + ((lane >> 3) << 2);
#pragma unroll
        for (int kk = 0; kk < 16; ++kk) {
            int c = 8 * kk + cb;
            float4 v = *(const float4*)(W_h + c * 128 + u0);
            sth(smc, B_WT, u0 + 0, c, __float2half_rn(v.x));
            sth(smc, B_WT, u0 + 1, c, __float2half_rn(v.y));
            sth(smc, B_WT, u0 + 2, c, __float2half_rn(v.z));
            sth(smc, B_WT, u0 + 3, c, __float2half_rn(v.w));
        }
    }
    if (tid < 128) {                    // x0 -> X0 (fp16, 32B rows, unswizzled)
        int p = tid;
        float4 f0 = *(const float4*)(feat + ((size_t)b * 128 + p) * 8);
        float4 f1 = *(const float4*)(feat + ((size_t)b * 128 + p) * 8 + 4);
        int pg = pdg[(size_t)b * 128 + p];
        float4 e0 = *(const float4*)(emb + pg * 8);
        float4 e1 = *(const float4*)(emb + pg * 8 + 4);
        __half2* d = (__half2*)(smc + B_X0 + p * 32);
        d[0] = __floats2half2_rn(f0.x, f0.y);
        d[1] = __floats2half2_rn(f0.z, f0.w);
        d[2] = __floats2half2_rn(f1.x, f1.y);
        d[3] = __floats2half2_rn(f1.z, f1.w);
        d[4] = __floats2half2_rn(e0.x, e0.y);
        d[5] = __floats2half2_rn(e0.z, e0.w);
        d[6] = __floats2half2_rn(e1.x, e1.y);
        d[7] = __floats2half2_rn(e1.z, e1.w);
    }
#pragma unroll
    for (int i = 0; i < 2; ++i) {       // W_in^T -> WINT (rows u, 16 halves)
        int idx = i * 256 + tid;
        int c = idx >> 5, u0 = (idx & 31) * 4;
        float4 wv = *(const float4*)(W_in + idx * 4);
        *(__half*)(smc + B_WINT + (u0 + 0) * 32 + c * 2) = __float2half_rn(wv.x);
        *(__half*)(smc + B_WINT + (u0 + 1) * 32 + c * 2) = __float2half_rn(wv.y);
        *(__half*)(smc + B_WINT + (u0 + 2) * 32 + c * 2) = __float2half_rn(wv.z);
        *(__half*)(smc + B_WINT + (u0 + 3) * 32 + c * 2) = __float2half_rn(wv.w);
    }
    if (tid < 192) {                    // b_h pre-scaled by 8^-(l+1)
        int l = tid >> 5;
        float s = exp2f(-3.0f * (float)(l + 1));
        float4 v = *(const float4*)(b_h + tid * 4);
        *(float4*)&smf[F_BIA + tid * 4] =
            make_float4(v.x * s, v.y * s, v.z * s, v.w * s);
    }
    if (tid < 32) {                     // b_in
        *(float4*)&smf[F_BIN + tid * 4] = *(const float4*)(b_in + tid * 4);
    } else if (tid < 64) {              // mask
        int q = tid - 32;
        *(float4*)&smf[F_MSK + q * 4] = *(const float4*)(mask + (size_t)b * 128 + q * 4);
    } else if (tid < 96) {              // W_out
        int q = tid - 64;
        *(float4*)&smf[F_WO + q * 4] = *(const float4*)(W_out + q * 4);
    } else if (tid == 96) {
        smf[F_BOUT] = b_out[0];
    }
    __syncthreads();

    if (warp == 0) {                    // denom -> F_DEN
        float s = smf[F_MSK + lane] + smf[F_MSK + lane + 32]
                + smf[F_MSK + lane + 64] + smf[F_MSK + lane + 96];
#pragma unroll
        for (int o = 16; o; o >>= 1) s += __shfl_down_sync(0xffffffffu, s, o);
        if (lane == 0) smf[F_DEN] = fmaxf(s, 1.0f);
    }

    // v = mask^T adj (column sums of masked adj), halves in F_PART
    {
        int n = tid & 127, h = tid >> 7;
        const int nb = (n >> 3), nlow = (n & 7) * 2;
        float s = 0.0f;
#pragma unroll
        for (int i = 0; i < 64; ++i) {
            int p = h * 64 + i;
            __half hv = *(const __half*)(smc + B_ADJ + p * 256
                         + ((nb ^ (p & 7)) << 4) + nlow);
            s += __half2float(hv) * smf[F_MSK + p];
        }
        smf[F_PART + h * 128 + n] = s;
    }

    float acc[4][4][4];

    uint32_t tACT[4], tADJ[4], tWT[4];
#pragma unroll
    for (int mt = 0; mt < 4; ++mt) {
        uint32_t rb = (uint32_t)(m0 + mt * 16 + aRow) * 256u;
        tADJ[mt] = SB + B_ADJ + rb;
        tACT[mt] = SB + B_ACT + rb;
        tWT[mt]  = SB + B_WT  + rb;
    }
    uint32_t nACT[2];
#pragma unroll
    for (int nb2 = 0; nb2 < 2; ++nb2) {
        uint32_t rb = (uint32_t)(n0 + nb2 * 16 + aRow) * 256u;
        nACT[nb2] = SB + B_ACT + rb;
    }

    // ================= input GEMM: X = x0 @ W_in + b_in (K=16, 1 step) =========
    {
        uint32_t A4[4][4], B4[2][4];
#pragma unroll
        for (int mt = 0; mt < 4; ++mt)
            ldsm4(SB + B_X0 + (uint32_t)(m0 + mt * 16 + aRow) * 32u + csel * 16u,
                  A4[mt][0], A4[mt][1], A4[mt][2], A4[mt][3]);
#pragma unroll
        for (int nb2 = 0; nb2 < 2; ++nb2)
            ldsm4(SB + B_WINT + (uint32_t)(n0 + nb2 * 16 + aRow) * 32u + csel * 16u,
                  B4[nb2][0], B4[nb2][1], B4[nb2][2], B4[nb2][3]);
#pragma unroll
        for (int mt = 0; mt < 4; ++mt)
#pragma unroll
            for (int nt = 0; nt < 4; ++nt)
                mma16z(acc[mt][nt], A4[mt][0], A4[mt][1], A4[mt][2], A4[mt][3],
                       B4[nt >> 1][nt & 1], B4[nt >> 1][(nt & 1) + 2]);
    }
#pragma unroll
    for (int mt = 0; mt < 4; ++mt)
#pragma unroll
        for (int nt = 0; nt < 4; ++nt) {
            int u0 = n0 + nt * 8 + ec;
            int ad = ebase + mt * 4096 + ch4[nt];
            float bi0 = smf[F_BIN + u0], bi1 = smf[F_BIN + u0 + 1];
            *(__half2*)(smc + ad) =
                __floats2half2_rn(acc[mt][nt][0] + bi0, acc[mt][nt][1] + bi1);
            *(__half2*)(smc + ad + 2048) =
                __floats2half2_rn(acc[mt][nt][2] + bi0, acc[mt][nt][3] + bi1);
        }
    __syncthreads();

    // ================= hidden layers 0..4 (full) =================
#pragma unroll 1
    for (int l = 0; l < NHID - 1; ++l) {
        // GEMM1 (flipped): Y^T[u][p] : A = WT (rows u), B^T = X (rows p, kh=u)
        gemm128<false>(tWT, nACT, acc, nullptr, smc, warp, lane, csel, rl);
        __syncthreads();
        // epi1: Ytilde = relu(acc*0.125 + b*8^-(l+1)); store Y^T (rows u, kh=p)
#pragma unroll
        for (int mt = 0; mt < 4; ++mt) {
            int u0 = m0 + mt * 16 + er;
            float bi  = smf[F_BIA + l * 128 + u0];
            float bi8 = smf[F_BIA + l * 128 + u0 + 8];
#pragma unroll
            for (int nt = 0; nt < 4; ++nt) {
                int ad = ebase + mt * 4096 + ch4[nt];
                *(__half2*)(smc + ad) =
                    __floats2half2_rn(fmaxf(acc[mt][nt][0] * 0.125f + bi, 0.0f),
                                      fmaxf(acc[mt][nt][1] * 0.125f + bi, 0.0f));
                *(__half2*)(smc + ad + 2048) =
                    __floats2half2_rn(fmaxf(acc[mt][nt][2] * 0.125f + bi8, 0.0f),
                                      fmaxf(acc[mt][nt][3] * 0.125f + bi8, 0.0f));
            }
        }
        __syncthreads();

        // GEMM2: X'[p][u] : A = ADJ (rows p), B^T = Y^T (rows u, kh=p)
        // (+ prefetch W_h[l+1] into WT; l+1 <= 5 always here)
        gemm128<true>(tADJ, nACT, acc, W_h + (size_t)(l + 1) * 16384,
                      smc, warp, lane, csel, rl);
        __syncthreads();
#pragma unroll
        for (int mt = 0; mt < 4; ++mt)
#pragma unroll
            for (int nt = 0; nt < 4; ++nt) {
                int ad = ebase + mt * 4096 + ch4[nt];
                *(__half2*)(smc + ad) =
                    __floats2half2_rn(acc[mt][nt][0], acc[mt][nt][1]);
                *(__half2*)(smc + ad + 2048) =
                    __floats2half2_rn(acc[mt][nt][2], acc[mt][nt][3]);
            }
        __syncthreads();
    }

    // ================= layer 5: dense GEMM + relu only =================
    gemm128<false>(tWT, nACT, acc, nullptr, smc, warp, lane, csel, rl);
    __syncthreads();
#pragma unroll
    for (int mt = 0; mt < 4; ++mt) {
        int u0 = m0 + mt * 16 + er;
        float bi  = smf[F_BIA + 5 * 128 + u0];
        float bi8 = smf[F_BIA + 5 * 128 + u0 + 8];
#pragma unroll
        for (int nt = 0; nt < 4; ++nt) {
            int ad = ebase + mt * 4096 + ch4[nt];
            *(__half2*)(smc + ad) =
                __floats2half2_rn(fmaxf(acc[mt][nt][0] * 0.125f + bi, 0.0f),
                                  fmaxf(acc[mt][nt][1] * 0.125f + bi, 0.0f));
            *(__half2*)(smc + ad + 2048) =
                __floats2half2_rn(fmaxf(acc[mt][nt][2] * 0.125f + bi8, 0.0f),
                                  fmaxf(acc[mt][nt][3] * 0.125f + bi8, 0.0f));
        }
    }
    __syncthreads();

    // VF[p] = v[p] (combine halves) into F_BIN (b_in dead)
    if (tid < 128)
        smf[F_BIN + tid] = smf[F_PART + tid] + smf[F_PART + 128 + tid];
    __syncthreads();

    // ================= pooled = v^T Ytilde6 * 2^18 / denom; out = pooled@W_out ==
    {
        int u = tid >> 1, h = tid & 1;
        const int ub = (u >> 3);
        const int ulow = (u & 7) * 2;
        float s = 0.0f;
#pragma unroll
        for (int j = 0; j < 32; ++j) {
            int p = h * 64 + j * 2;
            __half2 hv = *(const __half2*)(smc + B_ACT + u * 256
                          + (((p >> 3) ^ (u & 7)) << 4) + (p & 7) * 2);
            float2 f = __half22float2(hv);
            s += f.x * smf[F_BIN + p] + f.y * smf[F_BIN + p + 1];
        }
        (void)ub; (void)ulow;
        s += __shfl_xor_sync(0xffffffffu, s, 1);
        float val = (lane & 1) ? 0.0f
                  : s * 262144.0f / smf[F_DEN] * smf[F_WO + u];
#pragma unroll
        for (int o = 16; o; o >>= 1) val += __shfl_down_sync(0xffffffffu, val, o);
        if (lane == 0) smf[F_RED + warp] = val;
    }
    __syncthreads();
    if (tid == 0) {
        float r = 0.0f;
#pragma unroll
        for (int w = 0; w < 8; ++w) r += smf[F_RED + w];
        out[b] = r + smf[F_BOUT];
    }
}

extern "C" void kernel_launch(void* const* d_in, const int* in_sizes, int n_in,
                              void* d_out, int out_size)
{
    const int*   pdg   = (const int*)  d_in[0];
    const float* feat  = (const float*)d_in[1];
    const float* adjp  = (const float*)d_in[2];
    const float* maskp = (const float*)d_in[3];
    const float* emb   = (const float*)d_in[4];
    const float* W_in  = (const float*)d_in[5];
    const float* b_in  = (const float*)d_in[6];
    const float* W_h   = (const float*)d_in[7];
    const float* b_h   = (const float*)d_in[8];
    const float* W_out = (const float*)d_in[9];
    const float* b_out = (const float*)d_in[10];
    float* out = (float*)d_out;

    const int B = in_sizes[0] / 128;

    cudaFuncSetAttribute(gcn_mma_kernel,
                         cudaFuncAttributeMaxDynamicSharedMemorySize, SMEM_BYTES);
    gcn_mma_kernel<<<B, NTH, SMEM_BYTES>>>(
        pdg, feat, adjp, maskp, emb, W_in, b_in, W_h, b_h, W_out, b_out, out);
}